// round 6
// baseline (speedup 1.0000x reference)
#include <cuda_runtime.h>
#include <cuda_fp16.h>
#include <cstdint>

#define A_N 4
#define E_N 128
#define S_N 3072
#define NPIX (512 * 256)              // 131072
#define THREADS 1024
#define RPT 4                         // pixels per thread (register-resident acc)
#define TILE_PX (THREADS * RPT)       // 4096 pixels per CTA
#define NTILE (NPIX / TILE_PX)        // 32
#define NGROUP 4                      // split-K groups of 32 elements
#define EPC (E_N / NGROUP)            // 32 elements per CTA
#define EPP 2                         // elements per phase (per smem buffer)
#define NPHASE (EPC / EPP)            // 16
#define GRID (NTILE * NGROUP)         // 128
#define R4 (S_N / 4)                  // 768 float4 per rf row
#define ROWS_PB (EPP * A_N)           // 8 rows per buffer
#define BUF_F4 (ROWS_PB * R4)         // 6144 float4 per buffer (96KB)
#define SMEM_BYTES (2 * BUF_F4 * 16)  // 196608

// Partial sums: [NGROUP, A_N, NPIX] = 8MB scratch
__device__ float g_partial[NGROUP * A_N * NPIX];

__global__ void __launch_bounds__(THREADS, 1)
das_main(const float* __restrict__ d_tx, const float* __restrict__ d_rx,
         const float* __restrict__ apod, const float* __restrict__ rf,
         const float* __restrict__ t0)
{
    extern __shared__ half2 smh[];     // 2 buffers x 8 rows x S_N half2-pairs

    const int tid   = threadIdx.x;
    const int group = blockIdx.x & (NGROUP - 1);
    const int tile  = blockIdx.x >> 2;
    const int ebase = group * EPC;
    const int p0    = tile * TILE_PX + tid;   // thread's pixel r -> p0 + r*THREADS

    // ---- stage 2 elements x 4 angles into buffer `buf` as half2 pairs ----
    auto stage = [&](int buf, int e) {   // e = global element of first row pair
#pragma unroll
        for (int k = 0; k < BUF_F4 / THREADS; k++) {     // 6 chunks/thread
            int c   = tid + k * THREADS;                 // 0..6143
            int ae  = c / R4;                            // 0..7 (= el*4 + a)
            int col = c - ae * R4;
            int a   = ae & 3;
            int el  = ae >> 2;                           // 0..1
            const float* grow = rf + ((size_t)a * E_N + e + el) * S_N;
            float4 v  = *(const float4*)(grow + col * 4);
            float  s4 = grow[min(col * 4 + 4, S_N - 1)];
            half2 q0 = __floats2half2_rn(v.x, v.y);
            half2 q1 = __floats2half2_rn(v.y, v.z);
            half2 q2 = __floats2half2_rn(v.z, v.w);
            half2 q3 = __floats2half2_rn(v.w, s4);
            uint4 pk;
            pk.x = *(unsigned*)&q0; pk.y = *(unsigned*)&q1;
            pk.z = *(unsigned*)&q2; pk.w = *(unsigned*)&q3;
            *(uint4*)(smh + ((size_t)buf * BUF_F4 + c) * 4) = pk;
        }
        asm volatile("cp.async.commit_group;\n" ::);  // no-op group marker (STS path)
    };

    // Per-pixel per-angle tx delay, loaded ONCE per CTA (register resident)
    float dtx[A_N][RPT];
    float acc[A_N][RPT];
#pragma unroll
    for (int a = 0; a < A_N; a++) {
        float t0a = t0[a];
#pragma unroll
        for (int r = 0; r < RPT; r++) {
            dtx[a][r] = d_tx[(size_t)a * NPIX + p0 + r * THREADS] - t0a;
            acc[a][r] = 0.0f;
        }
    }

    // Prologue: stage phase 0 into buffer 0 (plain STS; visible after barrier)
    stage(0, ebase);

    for (int ph = 0; ph < NPHASE; ph++) {
        __syncthreads();               // buf ph&1 staged & prev reads done
        if (ph + 1 < NPHASE)
            stage((ph + 1) & 1, ebase + (ph + 1) * EPP);  // overlaps compute

        const int e = ebase + ph * EPP;
        const half2* bufp = smh + (size_t)(ph & 1) * BUF_F4 * 4;

#pragma unroll
        for (int r = 0; r < RPT; r++) {
            const int p = p0 + r * THREADS;
            // per-element scalars (coalesced)
            float drx0 = d_rx[(size_t)e * NPIX + p];
            float ap0  = apod[(size_t)e * NPIX + p];
            float drx1 = d_rx[(size_t)(e + 1) * NPIX + p];
            float ap1  = apod[(size_t)(e + 1) * NPIX + p];
#pragma unroll
            for (int el = 0; el < EPP; el++) {
                float drx = el ? drx1 : drx0;
                float ap  = el ? ap1  : ap0;
#pragma unroll
                for (int a = 0; a < A_N; a++) {
                    const half2* row = bufp + (el * A_N + a) * S_N;
                    float delay = dtx[a][r] + drx;
                    float f  = floorf(delay);
                    float w  = delay - f;
                    int   i0 = (int)f;
                    i0 = min(max(i0, 0), S_N - 2);   // safety clamp
                    half2 pr = row[i0];               // (rf[i0], rf[i0+1])
                    float v0 = __low2float(pr);
                    float v1 = __high2float(pr);
                    float s  = fmaf(w, v1 - v0, v0);
                    acc[a][r] = fmaf(s, ap, acc[a][r]);
                }
            }
        }
    }

    // Write this group's partials (8MB total across grid)
#pragma unroll
    for (int a = 0; a < A_N; a++)
#pragma unroll
        for (int r = 0; r < RPT; r++)
            g_partial[((size_t)group * A_N + a) * NPIX + p0 + r * THREADS]
                = acc[a][r];
}

// Reduce 4 group-partials -> out[A_N, NPIX], float4 vectorized (10MB traffic)
__global__ void __launch_bounds__(256, 4)
das_reduce(float* __restrict__ out)
{
    const float4* p4 = (const float4*)g_partial;
    float4* o4 = (float4*)out;
    int idx = blockIdx.x * 256 + threadIdx.x;     // 0 .. A_N*NPIX/4 - 1
    const int stride4 = A_N * NPIX / 4;
    float4 s = {0.f, 0.f, 0.f, 0.f};
#pragma unroll
    for (int g = 0; g < NGROUP; g++) {
        float4 v = p4[(size_t)g * stride4 + idx];
        s.x += v.x; s.y += v.y; s.z += v.z; s.w += v.w;
    }
    o4[idx] = s;
}

extern "C" void kernel_launch(void* const* d_in, const int* in_sizes, int n_in,
                              void* d_out, int out_size)
{
    const float* d_tx = (const float*)d_in[0];   // [A, NZ, NX]
    const float* d_rx = (const float*)d_in[1];   // [E, NZ, NX]
    const float* apod = (const float*)d_in[2];   // [E, NZ, NX]
    const float* rf   = (const float*)d_in[3];   // [A, E, S]
    const float* t0   = (const float*)d_in[4];   // [A]
    float* out = (float*)d_out;                  // [A, NZ, NX]

    cudaFuncSetAttribute(das_main,
                         cudaFuncAttributeMaxDynamicSharedMemorySize,
                         SMEM_BYTES);

    das_main<<<GRID, THREADS, SMEM_BYTES>>>(d_tx, d_rx, apod, rf, t0);
    das_reduce<<<(A_N * NPIX / 4) / 256, 256>>>(out);
}

// round 7
// speedup vs baseline: 1.6690x; 1.6690x over previous
#include <cuda_runtime.h>
#include <cuda_fp16.h>
#include <cstdint>

#define A_N 4
#define E_N 128
#define S_N 3072
#define NPIX (512 * 256)              // 131072
#define THREADS 1024
#define RPT 4                         // pixels per thread (register acc)
#define TILE_PX (THREADS * RPT)       // 4096
#define NTILE (NPIX / TILE_PX)        // 32
#define NGROUP 4                      // split-K groups
#define EPC (E_N / NGROUP)            // 32 elements per CTA
#define NPHASE EPC                    // 1 element per phase
#define GRID (NTILE * NGROUP)         // 128
#define R4 (S_N / 4)                  // 768 uint4 per packed row
#define BUF_U4 (A_N * R4)             // 3072 uint4 per buffer (48KB)
#define NBUF 4
#define SMEM_BYTES (NBUF * BUF_U4 * 16)   // 196608

// Pre-packed rf: [A][E][S] half2 pairs, entry i = (rf[i], rf[i+1])  (6MB)
__device__ half2 g_packed[A_N * E_N * S_N];
// Partial sums: [NGROUP][A_N][NPIX]  (8MB)
__device__ float g_partial[NGROUP * A_N * NPIX];

__device__ __forceinline__ void cp_async16(void* smem_ptr, const void* gptr) {
    unsigned s = (unsigned)__cvta_generic_to_shared(smem_ptr);
    asm volatile("cp.async.cg.shared.global [%0], [%1], 16;\n" :: "r"(s), "l"(gptr));
}

// ---- pack rf (fp32) -> half2 pairs, once ----
__global__ void __launch_bounds__(256)
das_prepack(const float* __restrict__ rf)
{
    int c = blockIdx.x * 256 + threadIdx.x;     // uint4 index, 0..A*E*R4-1
    int row = c / R4;                            // a*E_N + e
    int col = c - row * R4;
    const float* grow = rf + (size_t)row * S_N;
    float4 v  = ((const float4*)grow)[col];
    float  s4 = grow[min(col * 4 + 4, S_N - 1)];
    half2 q0 = __floats2half2_rn(v.x, v.y);
    half2 q1 = __floats2half2_rn(v.y, v.z);
    half2 q2 = __floats2half2_rn(v.z, v.w);
    half2 q3 = __floats2half2_rn(v.w, s4);
    uint4 pk;
    pk.x = *(unsigned*)&q0; pk.y = *(unsigned*)&q1;
    pk.z = *(unsigned*)&q2; pk.w = *(unsigned*)&q3;
    ((uint4*)g_packed)[c] = pk;
}

__global__ void __launch_bounds__(THREADS, 1)
das_main(const float* __restrict__ d_tx, const float* __restrict__ d_rx,
         const float* __restrict__ apod, const float* __restrict__ t0)
{
    extern __shared__ half2 smh[];        // 4 buffers x 4 rows x S_N half2
    uint4* sm4 = (uint4*)smh;
    const uint4* gp4 = (const uint4*)g_packed;

    const int tid   = threadIdx.x;
    const int group = blockIdx.x & (NGROUP - 1);
    const int tile  = blockIdx.x >> 2;
    const int ebase = group * EPC;
    const int p0    = tile * TILE_PX + tid;

    // cp.async staging of one element (4 angle-rows, 48KB) into buffer `buf`
    auto stage = [&](int buf, int e) {
#pragma unroll
        for (int k = 0; k < BUF_U4 / THREADS; k++) {   // 3 chunks/thread
            int c   = tid + k * THREADS;               // 0..3071
            int a   = c / R4;
            int col = c - a * R4;
            cp_async16(&sm4[buf * BUF_U4 + c],
                       &gp4[((size_t)a * E_N + e) * R4 + col]);
        }
        asm volatile("cp.async.commit_group;\n" ::);
    };

    // Per-pixel per-angle tx delays, loaded once; register accumulators
    float dtx[A_N][RPT];
    float acc[A_N][RPT];
#pragma unroll
    for (int a = 0; a < A_N; a++) {
        float t0a = t0[a];
#pragma unroll
        for (int r = 0; r < RPT; r++) {
            dtx[a][r] = d_tx[(size_t)a * NPIX + p0 + r * THREADS] - t0a;
            acc[a][r] = 0.0f;
        }
    }

    // Depth-2 prologue
    stage(0, ebase);
    stage(1, ebase + 1);

    for (int ph = 0; ph < NPHASE; ph++) {
        // Hazard-safe: stage(ph+2) writes buf (ph+2)&3, last read at
        // compute(ph-2), fenced by the barrier at phase ph-1.
        if (ph + 2 < NPHASE) {
            stage((ph + 2) & 3, ebase + ph + 2);
            asm volatile("cp.async.wait_group 2;\n" ::);   // buf ph arrived
        } else if (ph + 2 == NPHASE) {
            asm volatile("cp.async.wait_group 1;\n" ::);
        } else {
            asm volatile("cp.async.wait_group 0;\n" ::);
        }
        __syncthreads();               // buf ph visible to all threads

        const int e = ebase + ph;
        const half2* bufp = smh + (size_t)(ph & 3) * A_N * S_N;

        // Hoisted scalar loads (8 LDGs, full MLP)
        float drx[RPT], ap[RPT];
#pragma unroll
        for (int r = 0; r < RPT; r++) {
            size_t off = (size_t)e * NPIX + p0 + r * THREADS;
            drx[r] = d_rx[off];
            ap[r]  = apod[off];
        }

#pragma unroll
        for (int r = 0; r < RPT; r++) {
#pragma unroll
            for (int a = 0; a < A_N; a++) {
                const half2* row = bufp + a * S_N;
                float delay = dtx[a][r] + drx[r];
                float f  = floorf(delay);
                float w  = delay - f;
                int   i0 = (int)f;
                i0 = min(max(i0, 0), S_N - 2);   // safety clamp (data in-range)
                half2 pr = row[i0];               // 1 LDS.32: (rf[i0], rf[i0+1])
                float v0 = __low2float(pr);
                float v1 = __high2float(pr);
                float s  = fmaf(w, v1 - v0, v0);
                acc[a][r] = fmaf(s, ap[r], acc[a][r]);
            }
        }
    }

    // Write this group's partials
#pragma unroll
    for (int a = 0; a < A_N; a++)
#pragma unroll
        for (int r = 0; r < RPT; r++)
            g_partial[((size_t)group * A_N + a) * NPIX + p0 + r * THREADS]
                = acc[a][r];
}

// Reduce 4 group-partials -> out[A_N, NPIX]
__global__ void __launch_bounds__(256, 6)
das_reduce(float* __restrict__ out)
{
    const float4* p4 = (const float4*)g_partial;
    float4* o4 = (float4*)out;
    int idx = blockIdx.x * 256 + threadIdx.x;     // 0 .. A_N*NPIX/4 - 1
    const int stride4 = A_N * NPIX / 4;
    float4 s = {0.f, 0.f, 0.f, 0.f};
#pragma unroll
    for (int g = 0; g < NGROUP; g++) {
        float4 v = p4[(size_t)g * stride4 + idx];
        s.x += v.x; s.y += v.y; s.z += v.z; s.w += v.w;
    }
    o4[idx] = s;
}

extern "C" void kernel_launch(void* const* d_in, const int* in_sizes, int n_in,
                              void* d_out, int out_size)
{
    const float* d_tx = (const float*)d_in[0];   // [A, NZ, NX]
    const float* d_rx = (const float*)d_in[1];   // [E, NZ, NX]
    const float* apod = (const float*)d_in[2];   // [E, NZ, NX]
    const float* rf   = (const float*)d_in[3];   // [A, E, S]
    const float* t0   = (const float*)d_in[4];   // [A]
    float* out = (float*)d_out;                  // [A, NZ, NX]

    cudaFuncSetAttribute(das_main,
                         cudaFuncAttributeMaxDynamicSharedMemorySize,
                         SMEM_BYTES);

    das_prepack<<<(A_N * E_N * R4) / 256, 256>>>(rf);
    das_main<<<GRID, THREADS, SMEM_BYTES>>>(d_tx, d_rx, apod, t0);
    das_reduce<<<(A_N * NPIX / 4) / 256, 256>>>(out);
}